// round 13
// baseline (speedup 1.0000x reference)
#include <cuda_runtime.h>
#include <cuda_fp16.h>
#include <stdint.h>
#include <math.h>

#define NNODES 50000
#define NEDGES 800000
#define NG     512
#define EPSBN  1e-5f
#define SCAN_B 512
#define NSCB   ((NNODES + SCAN_B - 1) / SCAN_B)   // 98

// ---------------- scratch (device globals; no allocations allowed) -----------
__device__ float4       g_T4 [NNODES * 64];   // layer-1 transform out (128 f)
__device__ float4       g_H14[NNODES * 64];   // layer activations (ping)
__device__ float4       g_H24[NNODES * 64];   // layer activations (pong)
__device__ __align__(16) __half g_Tsp [NNODES * 768];  // fp16-split A' (3K wide)
__device__ __align__(16) __half g_W2sp[384 * 256];     // fp16-split W2'
__device__ __align__(16) __half g_W3sp[768 * 256];     // fp16-split W3'
__device__ int          g_cnt[NNODES];
__device__ int          g_off[NNODES + 1];
__device__ int          g_curs[NNODES];
__device__ float        g_dis[NNODES];
__device__ int          g_srcS[NEDGES];
__device__ float        g_normS[NEDGES];
__device__ int          g_bsum[NSCB];
__device__ int          g_boff[NSCB];
__device__ float        g_psum[NG * 256];
__device__ unsigned int g_pmax[NG * 256];
__device__ float        g_pcnt[NG];
__device__ float        g_z  [NG * 512];
__device__ float        g_m1 [NG * 256];
__device__ float        g_m2 [NG * 128];

// ---------------- helpers -----------------------------------------------------
__device__ __forceinline__ unsigned long long pk2(float lo, float hi) {
    unsigned long long r;
    asm("mov.b64 %0, {%1, %2};" : "=l"(r) : "f"(lo), "f"(hi));
    return r;
}
__device__ __forceinline__ void fma2(unsigned long long& d,
                                     unsigned long long a, unsigned long long b) {
    asm("fma.rn.f32x2 %0, %1, %2, %3;" : "=l"(d) : "l"(a), "l"(b), "l"(d));
}
__device__ __forceinline__ float2 upk2(unsigned long long v) {
    float2 f;
    asm("mov.b64 {%0, %1}, %2;" : "=f"(f.x), "=f"(f.y) : "l"(v));
    return f;
}
__device__ __forceinline__ uint32_t s2u(const void* p) {
    return (uint32_t)__cvta_generic_to_shared(p);
}
__device__ __forceinline__ uint32_t packh(__half a, __half b) {
    uint32_t r;
    asm("mov.b32 %0, {%1, %2};" : "=r"(r)
        : "h"(__half_as_ushort(a)), "h"(__half_as_ushort(b)));
    return r;
}

// ---------------- graph preprocessing ----------------------------------------
__global__ void zero_kernel() {
    int i = blockIdx.x * blockDim.x + threadIdx.x;   // covers 131072
    if (i < NNODES)    g_cnt[i] = 0;
    if (i < NG * 256) { g_psum[i] = 0.f; g_pmax[i] = 0u; }
    if (i < NG)        g_pcnt[i] = 0.f;
}

__global__ void count_kernel(const int* __restrict__ dst) {
    int e = blockIdx.x * blockDim.x + threadIdx.x;
    if (e < NEDGES) atomicAdd(&g_cnt[dst[e]], 1);
}

__global__ void scanA_kernel() {
    __shared__ int sh[SCAN_B];
    int t = threadIdx.x;
    int i = blockIdx.x * SCAN_B + t;
    int v = (i < NNODES) ? g_cnt[i] : 0;
    sh[t] = v;
    __syncthreads();
#pragma unroll
    for (int d = 1; d < SCAN_B; d <<= 1) {
        int u = (t >= d) ? sh[t - d] : 0;
        __syncthreads();
        sh[t] += u;
        __syncthreads();
    }
    if (i < NNODES) g_off[i] = sh[t] - v;
    if (t == SCAN_B - 1) g_bsum[blockIdx.x] = sh[t];
}

__global__ void scanB_kernel() {
    __shared__ int sh[128];
    int t = threadIdx.x;
    int v = (t < NSCB) ? g_bsum[t] : 0;
    sh[t] = v;
    __syncthreads();
#pragma unroll
    for (int d = 1; d < 128; d <<= 1) {
        int u = (t >= d) ? sh[t - d] : 0;
        __syncthreads();
        sh[t] += u;
        __syncthreads();
    }
    if (t < NSCB) g_boff[t] = sh[t] - v;
}

__global__ void scanC_kernel() {
    int i = blockIdx.x * blockDim.x + threadIdx.x;
    if (i < NNODES) {
        int o = g_off[i] + g_boff[i / SCAN_B];
        g_off[i]  = o;
        g_curs[i] = o;
        g_dis[i]  = rsqrtf((float)g_cnt[i] + 1.0f);
    }
    if (i == 0) g_off[NNODES] = NEDGES;
}

__global__ void fill_kernel(const int* __restrict__ src,
                            const int* __restrict__ dst) {
    int e = blockIdx.x * blockDim.x + threadIdx.x;
    if (e < NEDGES) {
        int s = src[e], d = dst[e];
        int p = atomicAdd(&g_curs[d], 1);
        g_srcS[p]  = s;
        g_normS[p] = g_dis[s] * g_dis[d];
    }
}

// ---------------- fp16 weight split: B'[3k+{0,1,2}][n] = {bh, bl, bh} ---------
template <int WSEL>
__global__ void splitW_kernel(const float* __restrict__ W, int K, int N) {
    __half* out = (WSEL == 2) ? g_W2sp : g_W3sp;
    int idx = blockIdx.x * blockDim.x + threadIdx.x;
    if (idx >= K * N) return;
    int k = idx / N, n = idx - k * N;
    float a = W[idx];
    __half h = __float2half(a);
    __half l = __float2half(a - __half2float(h));
    out[(3 * k + 0) * N + n] = h;
    out[(3 * k + 1) * N + n] = l;
    out[(3 * k + 2) * N + n] = h;
}

// -------- tensor-core GEMM (EXACT R11 layout): C = A'[M,Kp] @ B'[Kp,Nn] -------
// block 64x64, 4 warps (2x2), warp tile 32x32, BK=32, mma.m16n8k16 f16->f32.
// WSEL: 2 -> g_W2sp, 3 -> g_W3sp.  OSEL: 1 -> g_H14, 2 -> g_H24.
template <int WSEL, int OSEL>
__global__ __launch_bounds__(128)
void hmma_kernel(const float* __restrict__ bias, const float* __restrict__ ga,
                 const float* __restrict__ be, const float* __restrict__ mu,
                 const float* __restrict__ va, int M, int Nn, int Kp) {
    const __half* Asp = g_Tsp;
    const __half* Bsp = (WSEL == 2) ? g_W2sp : g_W3sp;
    float* C = (OSEL == 1) ? (float*)g_H14 : (float*)g_H24;

    __shared__ __half As[64][40];   // 80B rows: 16B-aligned, conflict-free ldsm
    __shared__ __half Bs[32][72];   // 144B rows
    int tid = threadIdx.x, lane = tid & 31, warp = tid >> 5;
    int m0 = blockIdx.x * 64, n0 = blockIdx.y * 64;
    int wm = (warp >> 1) * 32, wn = (warp & 1) * 32;

    float acc[2][4][4];
#pragma unroll
    for (int a = 0; a < 2; a++)
#pragma unroll
        for (int b = 0; b < 4; b++)
#pragma unroll
            for (int c = 0; c < 4; c++) acc[a][b][c] = 0.f;

    for (int k0 = 0; k0 < Kp; k0 += 32) {
#pragma unroll
        for (int i = 0; i < 2; i++) {          // A tile: 64 rows x 32 halves
            int idx = tid + i * 128;
            int row = idx >> 2, seg = idx & 3;
            int gm = m0 + row;
            uint4 v = make_uint4(0, 0, 0, 0);
            if (gm < M) v = *(const uint4*)&Asp[(size_t)gm * Kp + k0 + seg * 8];
            *(uint4*)&As[row][seg * 8] = v;
        }
#pragma unroll
        for (int i = 0; i < 2; i++) {          // B tile: 32 rows x 64 halves
            int idx = tid + i * 128;
            int row = idx >> 3, seg = idx & 7;
            *(uint4*)&Bs[row][seg * 8] =
                *(const uint4*)&Bsp[(size_t)(k0 + row) * Nn + n0 + seg * 8];
        }
        __syncthreads();
#pragma unroll
        for (int ks = 0; ks < 32; ks += 16) {
            uint32_t af[2][4], bf[4][2];
#pragma unroll
            for (int mf = 0; mf < 2; mf++) {
                uint32_t addr = s2u(&As[wm + mf * 16 + (lane & 15)][ks + (lane >> 4) * 8]);
                asm volatile("ldmatrix.sync.aligned.m8n8.x4.shared.b16 {%0,%1,%2,%3}, [%4];"
                    : "=r"(af[mf][0]), "=r"(af[mf][1]), "=r"(af[mf][2]), "=r"(af[mf][3])
                    : "r"(addr));
            }
#pragma unroll
            for (int nf = 0; nf < 2; nf++) {
                uint32_t r0, r1, r2, r3;
                uint32_t addr = s2u(&Bs[ks + (lane & 15)][wn + nf * 16 + (lane >> 4) * 8]);
                asm volatile("ldmatrix.sync.aligned.m8n8.x4.trans.shared.b16 {%0,%1,%2,%3}, [%4];"
                    : "=r"(r0), "=r"(r1), "=r"(r2), "=r"(r3) : "r"(addr));
                bf[nf * 2][0] = r0;     bf[nf * 2][1] = r1;
                bf[nf * 2 + 1][0] = r2; bf[nf * 2 + 1][1] = r3;
            }
#pragma unroll
            for (int mf = 0; mf < 2; mf++)
#pragma unroll
                for (int ng = 0; ng < 4; ng++) {
                    asm volatile(
                        "mma.sync.aligned.m16n8k16.row.col.f32.f16.f16.f32 "
                        "{%0,%1,%2,%3}, {%4,%5,%6,%7}, {%8,%9}, {%0,%1,%2,%3};"
                        : "+f"(acc[mf][ng][0]), "+f"(acc[mf][ng][1]),
                          "+f"(acc[mf][ng][2]), "+f"(acc[mf][ng][3])
                        : "r"(af[mf][0]), "r"(af[mf][1]), "r"(af[mf][2]), "r"(af[mf][3]),
                          "r"(bf[ng][0]), "r"(bf[ng][1]));
                }
        }
        __syncthreads();
    }

    // epilogue: (acc + bias - mu)*s + be, ReLU
#pragma unroll
    for (int ng = 0; ng < 4; ng++) {
        int n = n0 + wn + ng * 8 + (lane & 3) * 2;
        float s0 = ga[n]     * rsqrtf(va[n]     + EPSBN);
        float s1 = ga[n + 1] * rsqrtf(va[n + 1] + EPSBN);
        float h0 = be[n]     + (bias[n]     - mu[n])     * s0;
        float h1 = be[n + 1] + (bias[n + 1] - mu[n + 1]) * s1;
#pragma unroll
        for (int mf = 0; mf < 2; mf++) {
            int m = m0 + wm + mf * 16 + (lane >> 2);
            if (m < M) {
                C[(size_t)m * Nn + n]     = fmaxf(acc[mf][ng][0] * s0 + h0, 0.f);
                C[(size_t)m * Nn + n + 1] = fmaxf(acc[mf][ng][1] * s1 + h1, 0.f);
            }
            if (m + 8 < M) {
                C[(size_t)(m + 8) * Nn + n]     = fmaxf(acc[mf][ng][2] * s0 + h0, 0.f);
                C[(size_t)(m + 8) * Nn + n + 1] = fmaxf(acc[mf][ng][3] * s1 + h1, 0.f);
            }
        }
    }
}

// ---------------- SIMT GEMM (layer 1 + MLP head) ------------------------------
// ACT: 0=none(+bias if given), 1=bias+GELU
// ASEL: 0=ext, 1=g_T4, 2=g_z, 3=g_m1 ; CSEL: 0=ext, 1=g_T4, 2=g_m1, 3=g_m2
template <int ACT, int ASEL, int CSEL>
__global__ void gemm_kernel(const float* __restrict__ Aext, const float* __restrict__ B,
                            const float* __restrict__ bias, float* __restrict__ Cext,
                            int M, int Nn, int K) {
    const float* A = (ASEL == 0) ? Aext :
                     (ASEL == 1) ? (const float*)g_T4 :
                     (ASEL == 2) ? (const float*)g_z  : (const float*)g_m1;
    float* C = (CSEL == 0) ? Cext :
               (CSEL == 1) ? (float*)g_T4 :
               (CSEL == 2) ? (float*)g_m1 : (float*)g_m2;

    __shared__ float As[16][64];
    __shared__ float Bs[16][64];
    int tid = threadIdx.x;
    int tx = tid & 15, ty = tid >> 4;
    int m0 = blockIdx.x * 64;
    int n0 = blockIdx.y * 64;

    int amI[4], akI[4], bkI[4], bnI[4];
#pragma unroll
    for (int r = 0; r < 4; r++) {
        int idx = tid + r * 256;
        amI[r] = idx >> 4; akI[r] = idx & 15;
        bkI[r] = idx >> 6; bnI[r] = idx & 63;
    }

    unsigned long long acc2[4][2];
#pragma unroll
    for (int i = 0; i < 4; i++) { acc2[i][0] = 0ull; acc2[i][1] = 0ull; }

    float aR[4], bR[4];
#pragma unroll
    for (int r = 0; r < 4; r++) {
        int gm = m0 + amI[r];
        aR[r] = (gm < M) ? A[(size_t)gm * K + akI[r]] : 0.f;
        int gn = n0 + bnI[r];
        bR[r] = (gn < Nn) ? B[(size_t)bkI[r] * Nn + gn] : 0.f;
    }

    for (int k0 = 0; k0 < K; k0 += 16) {
#pragma unroll
        for (int r = 0; r < 4; r++) {
            As[akI[r]][amI[r]] = aR[r];
            Bs[bkI[r]][bnI[r]] = bR[r];
        }
        __syncthreads();
        int kn = k0 + 16;
        if (kn < K) {
#pragma unroll
            for (int r = 0; r < 4; r++) {
                int gm = m0 + amI[r];
                aR[r] = (gm < M) ? A[(size_t)gm * K + kn + akI[r]] : 0.f;
                int gn = n0 + bnI[r];
                bR[r] = (gn < Nn) ? B[(size_t)(kn + bkI[r]) * Nn + gn] : 0.f;
            }
        }
#pragma unroll
        for (int k = 0; k < 16; k++) {
            unsigned long long b0 = *(const unsigned long long*)&Bs[k][tx * 4];
            unsigned long long b1 = *(const unsigned long long*)&Bs[k][tx * 4 + 2];
            float a0 = As[k][ty * 4 + 0];
            float a1 = As[k][ty * 4 + 1];
            float a2 = As[k][ty * 4 + 2];
            float a3 = As[k][ty * 4 + 3];
            unsigned long long p0 = pk2(a0, a0), p1 = pk2(a1, a1);
            unsigned long long p2 = pk2(a2, a2), p3 = pk2(a3, a3);
            fma2(acc2[0][0], p0, b0); fma2(acc2[0][1], p0, b1);
            fma2(acc2[1][0], p1, b0); fma2(acc2[1][1], p1, b1);
            fma2(acc2[2][0], p2, b0); fma2(acc2[2][1], p2, b1);
            fma2(acc2[3][0], p3, b0); fma2(acc2[3][1], p3, b1);
        }
        __syncthreads();
    }
#pragma unroll
    for (int i = 0; i < 4; i++) {
        int m = m0 + ty * 4 + i;
        if (m >= M) continue;
        float2 lo = upk2(acc2[i][0]);
        float2 hi = upk2(acc2[i][1]);
        float v[4] = {lo.x, lo.y, hi.x, hi.y};
#pragma unroll
        for (int j = 0; j < 4; j++) {
            int n = n0 + tx * 4 + j;
            if (n >= Nn) continue;
            float t = v[j];
            if (bias) t += bias[n];
            if (ACT == 1) t = 0.5f * t * (1.0f + erff(t * 0.70710678118654752f));
            C[(size_t)m * Nn + n] = t;
        }
    }
}

// final MLP layer: out[G, 6] = g_m2[G, 128] @ Wm3[128, 6] + bm3
__global__ void mlp3_kernel(const float* __restrict__ Wm3,
                            const float* __restrict__ bm3,
                            float* __restrict__ out) {
    int idx = blockIdx.x * blockDim.x + threadIdx.x;
    if (idx >= NG * 6) return;
    int m = idx / 6, n = idx % 6;
    const float* row = &g_m2[m * 128];
    float s = 0.f;
#pragma unroll 8
    for (int k = 0; k < 128; k++) s += row[k] * Wm3[k * 6 + n];
    out[idx] = s + bm3[n];
}

// ------- agg with BN+ReLU epilogue (layer 1: reads g_T4, writes g_H14) -------
template <int D4>
__global__ void aggBN_kernel(const float* __restrict__ b,  const float* __restrict__ ga,
                             const float* __restrict__ be, const float* __restrict__ mm,
                             const float* __restrict__ vv) {
    constexpr int NODES = 256 / D4;
    int node = blockIdx.x * NODES + (threadIdx.x / D4);
    int c    = threadIdx.x & (D4 - 1);
    if (node >= NNODES) return;

    float dn = g_dis[node];
    float w0 = dn * dn;
    float4 t = g_T4[(size_t)node * D4 + c];
    float4 acc = make_float4(t.x * w0, t.y * w0, t.z * w0, t.w * w0);

    int e = g_off[node], e1 = g_off[node + 1];
    for (; e + 4 <= e1; e += 4) {
        int s0 = g_srcS[e], s1 = g_srcS[e+1], s2 = g_srcS[e+2], s3 = g_srcS[e+3];
        float n0 = g_normS[e], n1 = g_normS[e+1], n2 = g_normS[e+2], n3 = g_normS[e+3];
        float4 t0 = g_T4[(size_t)s0 * D4 + c];
        float4 t1 = g_T4[(size_t)s1 * D4 + c];
        float4 t2 = g_T4[(size_t)s2 * D4 + c];
        float4 t3 = g_T4[(size_t)s3 * D4 + c];
        acc.x += t0.x*n0 + t1.x*n1 + t2.x*n2 + t3.x*n3;
        acc.y += t0.y*n0 + t1.y*n1 + t2.y*n2 + t3.y*n3;
        acc.z += t0.z*n0 + t1.z*n1 + t2.z*n2 + t3.z*n3;
        acc.w += t0.w*n0 + t1.w*n1 + t2.w*n2 + t3.w*n3;
    }
    for (; e < e1; e++) {
        int   s = g_srcS[e];
        float w = g_normS[e];
        float4 ts = g_T4[(size_t)s * D4 + c];
        acc.x += ts.x * w; acc.y += ts.y * w;
        acc.z += ts.z * w; acc.w += ts.w * w;
    }

    float4 o;
#pragma unroll
    for (int q = 0; q < 4; q++) {
        int n = c * 4 + q;
        float s  = ga[n] * rsqrtf(vv[n] + EPSBN);
        float v  = ((&acc.x)[q] + b[n] - mm[n]) * s + be[n];
        (&o.x)[q] = fmaxf(v, 0.f);
    }
    g_H14[(size_t)node * D4 + c] = o;
}

// ------- agg + fp16 split epilogue: reads H-buffer, writes g_Tsp triplets ----
// output layout: g_Tsp[node*3K + 3k + {0,1,2}] = {h, h, l} for feature k.
// ISEL: 1 -> g_H14, 2 -> g_H24.  K = 4*D4.
template <int D4, int ISEL>
__global__ void aggSP_kernel() {
    const float4* In = (ISEL == 1) ? g_H14 : g_H24;
    constexpr int NODES = 256 / D4;
    constexpr int K = 4 * D4;
    int node = blockIdx.x * NODES + (threadIdx.x / D4);
    int c    = threadIdx.x & (D4 - 1);
    if (node >= NNODES) return;

    float dn = g_dis[node];
    float w0 = dn * dn;
    float4 t = In[(size_t)node * D4 + c];
    float4 acc = make_float4(t.x * w0, t.y * w0, t.z * w0, t.w * w0);

    int e = g_off[node], e1 = g_off[node + 1];
    for (; e + 4 <= e1; e += 4) {
        int s0 = g_srcS[e], s1 = g_srcS[e+1], s2 = g_srcS[e+2], s3 = g_srcS[e+3];
        float n0 = g_normS[e], n1 = g_normS[e+1], n2 = g_normS[e+2], n3 = g_normS[e+3];
        float4 t0 = In[(size_t)s0 * D4 + c];
        float4 t1 = In[(size_t)s1 * D4 + c];
        float4 t2 = In[(size_t)s2 * D4 + c];
        float4 t3 = In[(size_t)s3 * D4 + c];
        acc.x += t0.x*n0 + t1.x*n1 + t2.x*n2 + t3.x*n3;
        acc.y += t0.y*n0 + t1.y*n1 + t2.y*n2 + t3.y*n3;
        acc.z += t0.z*n0 + t1.z*n1 + t2.z*n2 + t3.z*n3;
        acc.w += t0.w*n0 + t1.w*n1 + t2.w*n2 + t3.w*n3;
    }
    for (; e < e1; e++) {
        int   s = g_srcS[e];
        float w = g_normS[e];
        float4 ts = In[(size_t)s * D4 + c];
        acc.x += ts.x * w; acc.y += ts.y * w;
        acc.z += ts.z * w; acc.w += ts.w * w;
    }

    // fp16 split epilogue: 4 floats -> 12 halves [h,h,l]x4 at 3*(c*4)
    __half h0 = __float2half(acc.x), l0 = __float2half(acc.x - __half2float(h0));
    __half h1 = __float2half(acc.y), l1 = __float2half(acc.y - __half2float(h1));
    __half h2 = __float2half(acc.z), l2 = __float2half(acc.z - __half2float(h2));
    __half h3 = __float2half(acc.w), l3 = __float2half(acc.w - __half2float(h3));
    uint2 w0v, w1v, w2v;
    w0v.x = packh(h0, h0); w0v.y = packh(l0, h1);
    w1v.x = packh(h1, l1); w1v.y = packh(h2, h2);
    w2v.x = packh(l2, h3); w2v.y = packh(h3, l3);
    __half* dstp = &g_Tsp[(size_t)node * 3 * K + (size_t)c * 12];
    *(uint2*)(dstp)     = w0v;
    *(uint2*)(dstp + 4) = w1v;
    *(uint2*)(dstp + 8) = w2v;
}

// ---------------- pooling (batch is sorted -> run-length flush) ---------------
__global__ void pool_feat_kernel(const int* __restrict__ batch) {
    int c  = threadIdx.x;
    int i0 = blockIdx.x * 64;
    if (i0 >= NNODES) return;
    int i1 = min(i0 + 64, NNODES);
    int cur = batch[i0];
    float4 s  = make_float4(0, 0, 0, 0);
    float4 mx = make_float4(0, 0, 0, 0);
    for (int i = i0; i < i1; i++) {
        int g = batch[i];
        if (g != cur) {
            int base = cur * 256 + c * 4;
            atomicAdd(&g_psum[base + 0], s.x); atomicAdd(&g_psum[base + 1], s.y);
            atomicAdd(&g_psum[base + 2], s.z); atomicAdd(&g_psum[base + 3], s.w);
            atomicMax(&g_pmax[base + 0], __float_as_uint(mx.x));
            atomicMax(&g_pmax[base + 1], __float_as_uint(mx.y));
            atomicMax(&g_pmax[base + 2], __float_as_uint(mx.z));
            atomicMax(&g_pmax[base + 3], __float_as_uint(mx.w));
            cur = g; s = make_float4(0, 0, 0, 0); mx = make_float4(0, 0, 0, 0);
        }
        float4 hv = g_H14[(size_t)i * 64 + c];
        s.x += hv.x; s.y += hv.y; s.z += hv.z; s.w += hv.w;
        mx.x = fmaxf(mx.x, hv.x); mx.y = fmaxf(mx.y, hv.y);
        mx.z = fmaxf(mx.z, hv.z); mx.w = fmaxf(mx.w, hv.w);
    }
    int base = cur * 256 + c * 4;
    atomicAdd(&g_psum[base + 0], s.x); atomicAdd(&g_psum[base + 1], s.y);
    atomicAdd(&g_psum[base + 2], s.z); atomicAdd(&g_psum[base + 3], s.w);
    atomicMax(&g_pmax[base + 0], __float_as_uint(mx.x));
    atomicMax(&g_pmax[base + 1], __float_as_uint(mx.y));
    atomicMax(&g_pmax[base + 2], __float_as_uint(mx.z));
    atomicMax(&g_pmax[base + 3], __float_as_uint(mx.w));
}

__global__ void pool_cnt_kernel(const int* __restrict__ batch) {
    int t  = blockIdx.x * blockDim.x + threadIdx.x;
    int i0 = t * 64;
    if (i0 >= NNODES) return;
    int i1 = min(i0 + 64, NNODES);
    int cur = batch[i0];
    int run = 0;
    for (int i = i0; i < i1; i++) {
        int g = batch[i];
        if (g != cur) { atomicAdd(&g_pcnt[cur], (float)run); cur = g; run = 0; }
        run++;
    }
    atomicAdd(&g_pcnt[cur], (float)run);
}

__global__ void finalize_z_kernel() {
    int idx = blockIdx.x * blockDim.x + threadIdx.x;
    if (idx >= NG * 512) return;
    int g = idx >> 9, c = idx & 511;
    if (c < 256) g_z[idx] = g_psum[g * 256 + c] / fmaxf(g_pcnt[g], 1.0f);
    else         g_z[idx] = __uint_as_float(g_pmax[g * 256 + (c - 256)]);
}

// ---------------- launch ------------------------------------------------------
extern "C" void kernel_launch(void* const* d_in, const int* in_sizes, int n_in,
                              void* d_out, int out_size) {
    const float* x     = (const float*)d_in[0];
    const int*   ei    = (const int*)d_in[1];
    const int*   batch = (const int*)d_in[2];
    const float *W1 = (const float*)d_in[3],  *b1 = (const float*)d_in[4],
                *ga1 = (const float*)d_in[5], *be1 = (const float*)d_in[6],
                *m1 = (const float*)d_in[7],  *v1 = (const float*)d_in[8];
    const float *W2 = (const float*)d_in[9],  *b2 = (const float*)d_in[10],
                *ga2 = (const float*)d_in[11],*be2 = (const float*)d_in[12],
                *m2 = (const float*)d_in[13], *v2 = (const float*)d_in[14];
    const float *W3 = (const float*)d_in[15], *b3 = (const float*)d_in[16],
                *ga3 = (const float*)d_in[17],*be3 = (const float*)d_in[18],
                *m3 = (const float*)d_in[19], *v3 = (const float*)d_in[20];
    const float *Wm1 = (const float*)d_in[21], *bm1 = (const float*)d_in[22];
    const float *Wm2 = (const float*)d_in[23], *bm2 = (const float*)d_in[24];
    const float *Wm3 = (const float*)d_in[25], *bm3 = (const float*)d_in[26];
    float* out = (float*)d_out;

    const int* src = ei;
    const int* dst = ei + NEDGES;

    static cudaStream_t s2 = nullptr;
    static cudaEvent_t evF = nullptr, evJ = nullptr;
    if (s2 == nullptr) {
        cudaStreamCreateWithFlags(&s2, cudaStreamNonBlocking);
        cudaEventCreateWithFlags(&evF, cudaEventDisableTiming);
        cudaEventCreateWithFlags(&evJ, cudaEventDisableTiming);
    }

    // fork: preprocessing + weight splits in s2 overlap layer-1 GEMM in stream 0
    cudaEventRecord(evF, 0);
    cudaStreamWaitEvent(s2, evF, 0);

    zero_kernel<<<512, 256, 0, s2>>>();
    count_kernel<<<(NEDGES + 255) / 256, 256, 0, s2>>>(dst);
    scanA_kernel<<<NSCB, SCAN_B, 0, s2>>>();
    scanB_kernel<<<1, 128, 0, s2>>>();
    scanC_kernel<<<(NNODES + 255) / 256, 256, 0, s2>>>();
    fill_kernel<<<(NEDGES + 255) / 256, 256, 0, s2>>>(src, dst);
    pool_cnt_kernel<<<((NNODES + 63) / 64 + 255) / 256, 256, 0, s2>>>(batch);
    splitW_kernel<2><<<(128 * 256 + 255) / 256, 256, 0, s2>>>(W2, 128, 256);
    splitW_kernel<3><<<(256 * 256 + 255) / 256, 256, 0, s2>>>(W3, 256, 256);

    const int MB = (NNODES + 63) / 64;     // 782 row-tiles

    // layer 1 (transform-first; overlaps preprocessing): x@W1 -> T
    gemm_kernel<0, 0, 1><<<dim3(MB, 2), 256>>>(x, W1, nullptr, nullptr, NNODES, 128, 64);

    cudaEventRecord(evJ, s2);
    cudaStreamWaitEvent(0, evJ, 0);

    aggBN_kernel<32><<<(NNODES + 7) / 8, 256>>>(b1, ga1, be1, m1, v1);     // T->H1

    // layer 2 (agg-first, split fused in agg epilogue): agg(H1)->Tsp; Tsp@W2'->H2
    aggSP_kernel<32, 1><<<(NNODES + 7) / 8, 256>>>();
    hmma_kernel<2, 2><<<dim3(MB, 4), 128>>>(b2, ga2, be2, m2, v2, NNODES, 256, 384);

    // layer 3: agg(H2)->Tsp; Tsp@W3'->H3 (g_H14)
    aggSP_kernel<64, 2><<<(NNODES + 3) / 4, 256>>>();
    hmma_kernel<3, 1><<<dim3(MB, 4), 128>>>(b3, ga3, be3, m3, v3, NNODES, 256, 768);

    // pooling (reads g_H14)
    pool_feat_kernel<<<(NNODES + 63) / 64, 64>>>(batch);
    finalize_z_kernel<<<(NG * 512 + 255) / 256, 256>>>();

    // MLP head (SIMT, as in the 542.8us best)
    gemm_kernel<1, 2, 2><<<dim3(8, 4), 256>>>(nullptr, Wm1, bm1, nullptr, NG, 256, 512);
    gemm_kernel<1, 3, 3><<<dim3(8, 2), 256>>>(nullptr, Wm2, bm2, nullptr, NG, 128, 256);
    mlp3_kernel<<<(NG * 6 + 255) / 256, 256>>>(Wm3, bm3, out);
}

// round 15
// speedup vs baseline: 1.3567x; 1.3567x over previous
#include <cuda_runtime.h>
#include <cuda_fp16.h>
#include <stdint.h>
#include <math.h>

#define NNODES 50000
#define NEDGES 800000
#define NG     512
#define EPSBN  1e-5f
#define SCAN_B 512
#define NSCB   ((NNODES + SCAN_B - 1) / SCAN_B)   // 98

// ---------------- scratch (device globals; no allocations allowed) -----------
__device__ float4       g_T4 [NNODES * 64];   // intermediate (max 256 f wide)
__device__ float4       g_H14[NNODES * 64];   // layer activations (ping)
__device__ float4       g_H24[NNODES * 64];   // layer activations (pong)
__device__ __align__(16) __half g_Tsp [NNODES * 768];  // fp16-split A' (3K wide)
__device__ __align__(16) __half g_W2sp[384 * 256];     // fp16-split W2'
__device__ __align__(16) __half g_W3sp[768 * 256];     // fp16-split W3'
__device__ int          g_cnt[NNODES];
__device__ int          g_off[NNODES + 1];
__device__ int          g_curs[NNODES];
__device__ float        g_dis[NNODES];
__device__ int          g_srcS[NEDGES];
__device__ float        g_normS[NEDGES];
__device__ int          g_bsum[NSCB];
__device__ int          g_boff[NSCB];
__device__ float        g_psum[NG * 256];
__device__ unsigned int g_pmax[NG * 256];
__device__ float        g_pcnt[NG];
__device__ float        g_z  [NG * 512];
__device__ float        g_m1 [NG * 256];
__device__ float        g_m2 [NG * 128];

// ---------------- helpers -----------------------------------------------------
__device__ __forceinline__ unsigned long long pk2(float lo, float hi) {
    unsigned long long r;
    asm("mov.b64 %0, {%1, %2};" : "=l"(r) : "f"(lo), "f"(hi));
    return r;
}
__device__ __forceinline__ void fma2(unsigned long long& d,
                                     unsigned long long a, unsigned long long b) {
    asm("fma.rn.f32x2 %0, %1, %2, %3;" : "=l"(d) : "l"(a), "l"(b), "l"(d));
}
__device__ __forceinline__ float2 upk2(unsigned long long v) {
    float2 f;
    asm("mov.b64 {%0, %1}, %2;" : "=f"(f.x), "=f"(f.y) : "l"(v));
    return f;
}
__device__ __forceinline__ uint32_t s2u(const void* p) {
    return (uint32_t)__cvta_generic_to_shared(p);
}
__device__ __forceinline__ uint32_t packh(__half a, __half b) {
    uint32_t r;
    asm("mov.b32 %0, {%1, %2};" : "=r"(r)
        : "h"(__half_as_ushort(a)), "h"(__half_as_ushort(b)));
    return r;
}
__device__ __forceinline__ void cpasync16(uint32_t dst, const void* src, int nbytes) {
    asm volatile("cp.async.cg.shared.global [%0], [%1], 16, %2;"
                 :: "r"(dst), "l"(src), "r"(nbytes));
}

// ---------------- graph preprocessing ----------------------------------------
__global__ void zero_kernel() {
    int i = blockIdx.x * blockDim.x + threadIdx.x;   // covers 131072
    if (i < NNODES)    g_cnt[i] = 0;
    if (i < NG * 256) { g_psum[i] = 0.f; g_pmax[i] = 0u; }
    if (i < NG)        g_pcnt[i] = 0.f;
}

__global__ void count_kernel(const int* __restrict__ dst) {
    int e = blockIdx.x * blockDim.x + threadIdx.x;
    if (e < NEDGES) atomicAdd(&g_cnt[dst[e]], 1);
}

__global__ void scanA_kernel() {
    __shared__ int sh[SCAN_B];
    int t = threadIdx.x;
    int i = blockIdx.x * SCAN_B + t;
    int v = (i < NNODES) ? g_cnt[i] : 0;
    sh[t] = v;
    __syncthreads();
#pragma unroll
    for (int d = 1; d < SCAN_B; d <<= 1) {
        int u = (t >= d) ? sh[t - d] : 0;
        __syncthreads();
        sh[t] += u;
        __syncthreads();
    }
    if (i < NNODES) g_off[i] = sh[t] - v;
    if (t == SCAN_B - 1) g_bsum[blockIdx.x] = sh[t];
}

__global__ void scanB_kernel() {
    __shared__ int sh[128];
    int t = threadIdx.x;
    int v = (t < NSCB) ? g_bsum[t] : 0;
    sh[t] = v;
    __syncthreads();
#pragma unroll
    for (int d = 1; d < 128; d <<= 1) {
        int u = (t >= d) ? sh[t - d] : 0;
        __syncthreads();
        sh[t] += u;
        __syncthreads();
    }
    if (t < NSCB) g_boff[t] = sh[t] - v;
}

__global__ void scanC_kernel() {
    int i = blockIdx.x * blockDim.x + threadIdx.x;
    if (i < NNODES) {
        int o = g_off[i] + g_boff[i / SCAN_B];
        g_off[i]  = o;
        g_curs[i] = o;
        g_dis[i]  = rsqrtf((float)g_cnt[i] + 1.0f);
    }
    if (i == 0) g_off[NNODES] = NEDGES;
}

__global__ void fill_kernel(const int* __restrict__ src,
                            const int* __restrict__ dst) {
    int e = blockIdx.x * blockDim.x + threadIdx.x;
    if (e < NEDGES) {
        int s = src[e], d = dst[e];
        int p = atomicAdd(&g_curs[d], 1);
        g_srcS[p]  = s;
        g_normS[p] = g_dis[s] * g_dis[d];
    }
}

// ---------------- fp16 split pre-passes ---------------------------------------
// Flat identity: out_half[3f + {0,1,2}] = {h, h, l} for flat float index f.
// Coalesced form: one thread per output uint j = 3q + r covering floats 2q,2q+1.
__global__ void splitT_kernel(int total_uints) {
    int j = blockIdx.x * blockDim.x + threadIdx.x;
    if (j >= total_uints) return;
    int q = j / 3, r = j - q * 3;
    const float* Af = (const float*)g_T4;
    float f0 = Af[2 * q], f1 = Af[2 * q + 1];
    __half h0 = __float2half(f0), l0 = __float2half(f0 - __half2float(h0));
    __half h1 = __float2half(f1), l1 = __float2half(f1 - __half2float(h1));
    uint32_t u;
    if (r == 0)      u = packh(h0, h0);
    else if (r == 1) u = packh(l0, h1);
    else             u = packh(h1, l1);
    ((uint32_t*)g_Tsp)[j] = u;
}

template <int WSEL>
__global__ void splitW_kernel(const float* __restrict__ W, int K, int N) {
    __half* out = (WSEL == 2) ? g_W2sp : g_W3sp;
    int idx = blockIdx.x * blockDim.x + threadIdx.x;
    if (idx >= K * N) return;
    int k = idx / N, n = idx - k * N;
    float a = W[idx];
    __half h = __float2half(a);
    __half l = __float2half(a - __half2float(h));
    out[(3 * k + 0) * N + n] = h;
    out[(3 * k + 1) * N + n] = l;
    out[(3 * k + 2) * N + n] = h;
}

// -------- tensor-core GEMM (R11 smem layout + cp.async double buffering) ------
// C = A'[M,Kp] @ B'[Kp,Nn] + bias + BN + ReLU.  block 64x64, 4 warps (2x2),
// BK=32, mma.m16n8k16 f16->f32.  WSEL: 2/3.  OSEL: 1 -> g_H14, 2 -> g_H24.
template <int WSEL, int OSEL>
__global__ __launch_bounds__(128)
void hmma_kernel(const float* __restrict__ bias, const float* __restrict__ ga,
                 const float* __restrict__ be, const float* __restrict__ mu,
                 const float* __restrict__ va, int M, int Nn, int Kp) {
    const __half* Asp = g_Tsp;
    const __half* Bsp = (WSEL == 2) ? g_W2sp : g_W3sp;
    float* C = (OSEL == 1) ? (float*)g_H14 : (float*)g_H24;

    __shared__ __half As[2][64][40];   // 80B rows (same class as R11)
    __shared__ __half Bs[2][32][72];   // 144B rows
    int tid = threadIdx.x, lane = tid & 31, warp = tid >> 5;
    int m0 = blockIdx.x * 64, n0 = blockIdx.y * 64;
    int wm = (warp >> 1) * 32, wn = (warp & 1) * 32;

    float acc[2][4][4];
#pragma unroll
    for (int a = 0; a < 2; a++)
#pragma unroll
        for (int b = 0; b < 4; b++)
#pragma unroll
            for (int c = 0; c < 4; c++) acc[a][b][c] = 0.f;

    // per-thread load coordinates (same mapping as R11)
    int arow0 = tid >> 2,          aseg0 = tid & 3;         // +  i*128 -> arow+32
    int brow0 = tid >> 3,          bseg0 = tid & 7;         // +  i*128 -> brow+16

    const int NIT = Kp / 32;
    for (int it = 0; it <= NIT; it++) {
        if (it < NIT) {                 // preload tile `it` into buf it&1
            int buf = it & 1;
            int k0 = it * 32;
#pragma unroll
            for (int i = 0; i < 2; i++) {
                int row = arow0 + i * 32;
                int gm = m0 + row;
                int gmc = (gm < M) ? gm : (M - 1);
                cpasync16(s2u(&As[buf][row][aseg0 * 8]),
                          &Asp[(size_t)gmc * Kp + k0 + aseg0 * 8],
                          (gm < M) ? 16 : 0);
            }
#pragma unroll
            for (int i = 0; i < 2; i++) {
                int row = brow0 + i * 16;
                cpasync16(s2u(&Bs[buf][row][bseg0 * 8]),
                          &Bsp[(size_t)(k0 + row) * Nn + n0 + bseg0 * 8], 16);
            }
            asm volatile("cp.async.commit_group;");
        }
        if (it >= 1) {                  // compute tile it-1 from buf (it-1)&1
            if (it < NIT) asm volatile("cp.async.wait_group 1;");
            else          asm volatile("cp.async.wait_group 0;");
            __syncthreads();
            int buf = (it - 1) & 1;
#pragma unroll
            for (int ks = 0; ks < 32; ks += 16) {
                uint32_t af[2][4], bf[4][2];
#pragma unroll
                for (int mf = 0; mf < 2; mf++) {
                    uint32_t addr = s2u(&As[buf][wm + mf * 16 + (lane & 15)][ks + (lane >> 4) * 8]);
                    asm volatile("ldmatrix.sync.aligned.m8n8.x4.shared.b16 {%0,%1,%2,%3}, [%4];"
                        : "=r"(af[mf][0]), "=r"(af[mf][1]), "=r"(af[mf][2]), "=r"(af[mf][3])
                        : "r"(addr));
                }
#pragma unroll
                for (int nf = 0; nf < 2; nf++) {
                    uint32_t r0, r1, r2, r3;
                    uint32_t addr = s2u(&Bs[buf][ks + (lane & 15)][wn + nf * 16 + (lane >> 4) * 8]);
                    asm volatile("ldmatrix.sync.aligned.m8n8.x4.trans.shared.b16 {%0,%1,%2,%3}, [%4];"
                        : "=r"(r0), "=r"(r1), "=r"(r2), "=r"(r3) : "r"(addr));
                    bf[nf * 2][0] = r0;     bf[nf * 2][1] = r1;
                    bf[nf * 2 + 1][0] = r2; bf[nf * 2 + 1][1] = r3;
                }
#pragma unroll
                for (int mf = 0; mf < 2; mf++)
#pragma unroll
                    for (int ng = 0; ng < 4; ng++) {
                        asm volatile(
                            "mma.sync.aligned.m16n8k16.row.col.f32.f16.f16.f32 "
                            "{%0,%1,%2,%3}, {%4,%5,%6,%7}, {%8,%9}, {%0,%1,%2,%3};"
                            : "+f"(acc[mf][ng][0]), "+f"(acc[mf][ng][1]),
                              "+f"(acc[mf][ng][2]), "+f"(acc[mf][ng][3])
                            : "r"(af[mf][0]), "r"(af[mf][1]), "r"(af[mf][2]), "r"(af[mf][3]),
                              "r"(bf[ng][0]), "r"(bf[ng][1]));
                    }
            }
            __syncthreads();
        }
    }

    // epilogue: (acc + bias - mu)*s + be, ReLU
#pragma unroll
    for (int ng = 0; ng < 4; ng++) {
        int n = n0 + wn + ng * 8 + (lane & 3) * 2;
        float s0 = ga[n]     * rsqrtf(va[n]     + EPSBN);
        float s1 = ga[n + 1] * rsqrtf(va[n + 1] + EPSBN);
        float h0 = be[n]     + (bias[n]     - mu[n])     * s0;
        float h1 = be[n + 1] + (bias[n + 1] - mu[n + 1]) * s1;
#pragma unroll
        for (int mf = 0; mf < 2; mf++) {
            int m = m0 + wm + mf * 16 + (lane >> 2);
            if (m < M) {
                C[(size_t)m * Nn + n]     = fmaxf(acc[mf][ng][0] * s0 + h0, 0.f);
                C[(size_t)m * Nn + n + 1] = fmaxf(acc[mf][ng][1] * s1 + h1, 0.f);
            }
            if (m + 8 < M) {
                C[(size_t)(m + 8) * Nn + n]     = fmaxf(acc[mf][ng][2] * s0 + h0, 0.f);
                C[(size_t)(m + 8) * Nn + n + 1] = fmaxf(acc[mf][ng][3] * s1 + h1, 0.f);
            }
        }
    }
}

// ---------------- SIMT GEMM (layer 1 + MLP head) ------------------------------
// ACT: 0=none(+bias if given), 1=bias+GELU
// ASEL: 0=ext, 1=g_T4, 2=g_z, 3=g_m1 ; CSEL: 0=ext, 1=g_T4, 2=g_m1, 3=g_m2
template <int ACT, int ASEL, int CSEL>
__global__ void gemm_kernel(const float* __restrict__ Aext, const float* __restrict__ B,
                            const float* __restrict__ bias, float* __restrict__ Cext,
                            int M, int Nn, int K) {
    const float* A = (ASEL == 0) ? Aext :
                     (ASEL == 1) ? (const float*)g_T4 :
                     (ASEL == 2) ? (const float*)g_z  : (const float*)g_m1;
    float* C = (CSEL == 0) ? Cext :
               (CSEL == 1) ? (float*)g_T4 :
               (CSEL == 2) ? (float*)g_m1 : (float*)g_m2;

    __shared__ float As[16][64];
    __shared__ float Bs[16][64];
    int tid = threadIdx.x;
    int tx = tid & 15, ty = tid >> 4;
    int m0 = blockIdx.x * 64;
    int n0 = blockIdx.y * 64;

    int amI[4], akI[4], bkI[4], bnI[4];
#pragma unroll
    for (int r = 0; r < 4; r++) {
        int idx = tid + r * 256;
        amI[r] = idx >> 4; akI[r] = idx & 15;
        bkI[r] = idx >> 6; bnI[r] = idx & 63;
    }

    unsigned long long acc2[4][2];
#pragma unroll
    for (int i = 0; i < 4; i++) { acc2[i][0] = 0ull; acc2[i][1] = 0ull; }

    float aR[4], bR[4];
#pragma unroll
    for (int r = 0; r < 4; r++) {
        int gm = m0 + amI[r];
        aR[r] = (gm < M) ? A[(size_t)gm * K + akI[r]] : 0.f;
        int gn = n0 + bnI[r];
        bR[r] = (gn < Nn) ? B[(size_t)bkI[r] * Nn + gn] : 0.f;
    }

    for (int k0 = 0; k0 < K; k0 += 16) {
#pragma unroll
        for (int r = 0; r < 4; r++) {
            As[akI[r]][amI[r]] = aR[r];
            Bs[bkI[r]][bnI[r]] = bR[r];
        }
        __syncthreads();
        int kn = k0 + 16;
        if (kn < K) {
#pragma unroll
            for (int r = 0; r < 4; r++) {
                int gm = m0 + amI[r];
                aR[r] = (gm < M) ? A[(size_t)gm * K + kn + akI[r]] : 0.f;
                int gn = n0 + bnI[r];
                bR[r] = (gn < Nn) ? B[(size_t)(kn + bkI[r]) * Nn + gn] : 0.f;
            }
        }
#pragma unroll
        for (int k = 0; k < 16; k++) {
            unsigned long long b0 = *(const unsigned long long*)&Bs[k][tx * 4];
            unsigned long long b1 = *(const unsigned long long*)&Bs[k][tx * 4 + 2];
            float a0 = As[k][ty * 4 + 0];
            float a1 = As[k][ty * 4 + 1];
            float a2 = As[k][ty * 4 + 2];
            float a3 = As[k][ty * 4 + 3];
            unsigned long long p0 = pk2(a0, a0), p1 = pk2(a1, a1);
            unsigned long long p2 = pk2(a2, a2), p3 = pk2(a3, a3);
            fma2(acc2[0][0], p0, b0); fma2(acc2[0][1], p0, b1);
            fma2(acc2[1][0], p1, b0); fma2(acc2[1][1], p1, b1);
            fma2(acc2[2][0], p2, b0); fma2(acc2[2][1], p2, b1);
            fma2(acc2[3][0], p3, b0); fma2(acc2[3][1], p3, b1);
        }
        __syncthreads();
    }
#pragma unroll
    for (int i = 0; i < 4; i++) {
        int m = m0 + ty * 4 + i;
        if (m >= M) continue;
        float2 lo = upk2(acc2[i][0]);
        float2 hi = upk2(acc2[i][1]);
        float v[4] = {lo.x, lo.y, hi.x, hi.y};
#pragma unroll
        for (int j = 0; j < 4; j++) {
            int n = n0 + tx * 4 + j;
            if (n >= Nn) continue;
            float t = v[j];
            if (bias) t += bias[n];
            if (ACT == 1) t = 0.5f * t * (1.0f + erff(t * 0.70710678118654752f));
            C[(size_t)m * Nn + n] = t;
        }
    }
}

// final MLP layer: out[G, 6] = g_m2[G, 128] @ Wm3[128, 6] + bm3
__global__ void mlp3_kernel(const float* __restrict__ Wm3,
                            const float* __restrict__ bm3,
                            float* __restrict__ out) {
    int idx = blockIdx.x * blockDim.x + threadIdx.x;
    if (idx >= NG * 6) return;
    int m = idx / 6, n = idx % 6;
    const float* row = &g_m2[m * 128];
    float s = 0.f;
#pragma unroll 8
    for (int k = 0; k < 128; k++) s += row[k] * Wm3[k * 6 + n];
    out[idx] = s + bm3[n];
}

// ------- agg with BN+ReLU epilogue (layer 1: reads g_T4, writes g_H14) -------
template <int D4>
__global__ void aggBN_kernel(const float* __restrict__ b,  const float* __restrict__ ga,
                             const float* __restrict__ be, const float* __restrict__ mm,
                             const float* __restrict__ vv) {
    constexpr int NODES = 256 / D4;
    int node = blockIdx.x * NODES + (threadIdx.x / D4);
    int c    = threadIdx.x & (D4 - 1);
    if (node >= NNODES) return;

    float dn = g_dis[node];
    float w0 = dn * dn;
    float4 t = g_T4[(size_t)node * D4 + c];
    float4 acc = make_float4(t.x * w0, t.y * w0, t.z * w0, t.w * w0);

    int e = g_off[node], e1 = g_off[node + 1];
    for (; e + 4 <= e1; e += 4) {
        int s0 = g_srcS[e], s1 = g_srcS[e+1], s2 = g_srcS[e+2], s3 = g_srcS[e+3];
        float n0 = g_normS[e], n1 = g_normS[e+1], n2 = g_normS[e+2], n3 = g_normS[e+3];
        float4 t0 = g_T4[(size_t)s0 * D4 + c];
        float4 t1 = g_T4[(size_t)s1 * D4 + c];
        float4 t2 = g_T4[(size_t)s2 * D4 + c];
        float4 t3 = g_T4[(size_t)s3 * D4 + c];
        acc.x += t0.x*n0 + t1.x*n1 + t2.x*n2 + t3.x*n3;
        acc.y += t0.y*n0 + t1.y*n1 + t2.y*n2 + t3.y*n3;
        acc.z += t0.z*n0 + t1.z*n1 + t2.z*n2 + t3.z*n3;
        acc.w += t0.w*n0 + t1.w*n1 + t2.w*n2 + t3.w*n3;
    }
    for (; e < e1; e++) {
        int   s = g_srcS[e];
        float w = g_normS[e];
        float4 ts = g_T4[(size_t)s * D4 + c];
        acc.x += ts.x * w; acc.y += ts.y * w;
        acc.z += ts.z * w; acc.w += ts.w * w;
    }

    float4 o;
#pragma unroll
    for (int q = 0; q < 4; q++) {
        int n = c * 4 + q;
        float s  = ga[n] * rsqrtf(vv[n] + EPSBN);
        float v  = ((&acc.x)[q] + b[n] - mm[n]) * s + be[n];
        (&o.x)[q] = fmaxf(v, 0.f);
    }
    g_H14[(size_t)node * D4 + c] = o;
}

// ------- plain agg (no epilogue): reads H-buffer, writes g_T4 ----------------
template <int D4, int ISEL>
__global__ void aggP_kernel() {
    const float4* In = (ISEL == 1) ? g_H14 : g_H24;
    constexpr int NODES = 256 / D4;
    int node = blockIdx.x * NODES + (threadIdx.x / D4);
    int c    = threadIdx.x & (D4 - 1);
    if (node >= NNODES) return;

    float dn = g_dis[node];
    float w0 = dn * dn;
    float4 t = In[(size_t)node * D4 + c];
    float4 acc = make_float4(t.x * w0, t.y * w0, t.z * w0, t.w * w0);

    int e = g_off[node], e1 = g_off[node + 1];
    for (; e + 4 <= e1; e += 4) {
        int s0 = g_srcS[e], s1 = g_srcS[e+1], s2 = g_srcS[e+2], s3 = g_srcS[e+3];
        float n0 = g_normS[e], n1 = g_normS[e+1], n2 = g_normS[e+2], n3 = g_normS[e+3];
        float4 t0 = In[(size_t)s0 * D4 + c];
        float4 t1 = In[(size_t)s1 * D4 + c];
        float4 t2 = In[(size_t)s2 * D4 + c];
        float4 t3 = In[(size_t)s3 * D4 + c];
        acc.x += t0.x*n0 + t1.x*n1 + t2.x*n2 + t3.x*n3;
        acc.y += t0.y*n0 + t1.y*n1 + t2.y*n2 + t3.y*n3;
        acc.z += t0.z*n0 + t1.z*n1 + t2.z*n2 + t3.z*n3;
        acc.w += t0.w*n0 + t1.w*n1 + t2.w*n2 + t3.w*n3;
    }
    for (; e < e1; e++) {
        int   s = g_srcS[e];
        float w = g_normS[e];
        float4 ts = In[(size_t)s * D4 + c];
        acc.x += ts.x * w; acc.y += ts.y * w;
        acc.z += ts.z * w; acc.w += ts.w * w;
    }
    g_T4[(size_t)node * D4 + c] = acc;
}

// ---------------- pooling (batch is sorted -> run-length flush) ---------------
__global__ void pool_feat_kernel(const int* __restrict__ batch) {
    int c  = threadIdx.x;
    int i0 = blockIdx.x * 64;
    if (i0 >= NNODES) return;
    int i1 = min(i0 + 64, NNODES);
    int cur = batch[i0];
    float4 s  = make_float4(0, 0, 0, 0);
    float4 mx = make_float4(0, 0, 0, 0);
    for (int i = i0; i < i1; i++) {
        int g = batch[i];
        if (g != cur) {
            int base = cur * 256 + c * 4;
            atomicAdd(&g_psum[base + 0], s.x); atomicAdd(&g_psum[base + 1], s.y);
            atomicAdd(&g_psum[base + 2], s.z); atomicAdd(&g_psum[base + 3], s.w);
            atomicMax(&g_pmax[base + 0], __float_as_uint(mx.x));
            atomicMax(&g_pmax[base + 1], __float_as_uint(mx.y));
            atomicMax(&g_pmax[base + 2], __float_as_uint(mx.z));
            atomicMax(&g_pmax[base + 3], __float_as_uint(mx.w));
            cur = g; s = make_float4(0, 0, 0, 0); mx = make_float4(0, 0, 0, 0);
        }
        float4 hv = g_H14[(size_t)i * 64 + c];
        s.x += hv.x; s.y += hv.y; s.z += hv.z; s.w += hv.w;
        mx.x = fmaxf(mx.x, hv.x); mx.y = fmaxf(mx.y, hv.y);
        mx.z = fmaxf(mx.z, hv.z); mx.w = fmaxf(mx.w, hv.w);
    }
    int base = cur * 256 + c * 4;
    atomicAdd(&g_psum[base + 0], s.x); atomicAdd(&g_psum[base + 1], s.y);
    atomicAdd(&g_psum[base + 2], s.z); atomicAdd(&g_psum[base + 3], s.w);
    atomicMax(&g_pmax[base + 0], __float_as_uint(mx.x));
    atomicMax(&g_pmax[base + 1], __float_as_uint(mx.y));
    atomicMax(&g_pmax[base + 2], __float_as_uint(mx.z));
    atomicMax(&g_pmax[base + 3], __float_as_uint(mx.w));
}

__global__ void pool_cnt_kernel(const int* __restrict__ batch) {
    int t  = blockIdx.x * blockDim.x + threadIdx.x;
    int i0 = t * 64;
    if (i0 >= NNODES) return;
    int i1 = min(i0 + 64, NNODES);
    int cur = batch[i0];
    int run = 0;
    for (int i = i0; i < i1; i++) {
        int g = batch[i];
        if (g != cur) { atomicAdd(&g_pcnt[cur], (float)run); cur = g; run = 0; }
        run++;
    }
    atomicAdd(&g_pcnt[cur], (float)run);
}

__global__ void finalize_z_kernel() {
    int idx = blockIdx.x * blockDim.x + threadIdx.x;
    if (idx >= NG * 512) return;
    int g = idx >> 9, c = idx & 511;
    if (c < 256) g_z[idx] = g_psum[g * 256 + c] / fmaxf(g_pcnt[g], 1.0f);
    else         g_z[idx] = __uint_as_float(g_pmax[g * 256 + (c - 256)]);
}

// ---------------- launch ------------------------------------------------------
extern "C" void kernel_launch(void* const* d_in, const int* in_sizes, int n_in,
                              void* d_out, int out_size) {
    const float* x     = (const float*)d_in[0];
    const int*   ei    = (const int*)d_in[1];
    const int*   batch = (const int*)d_in[2];
    const float *W1 = (const float*)d_in[3],  *b1 = (const float*)d_in[4],
                *ga1 = (const float*)d_in[5], *be1 = (const float*)d_in[6],
                *m1 = (const float*)d_in[7],  *v1 = (const float*)d_in[8];
    const float *W2 = (const float*)d_in[9],  *b2 = (const float*)d_in[10],
                *ga2 = (const float*)d_in[11],*be2 = (const float*)d_in[12],
                *m2 = (const float*)d_in[13], *v2 = (const float*)d_in[14];
    const float *W3 = (const float*)d_in[15], *b3 = (const float*)d_in[16],
                *ga3 = (const float*)d_in[17],*be3 = (const float*)d_in[18],
                *m3 = (const float*)d_in[19], *v3 = (const float*)d_in[20];
    const float *Wm1 = (const float*)d_in[21], *bm1 = (const float*)d_in[22];
    const float *Wm2 = (const float*)d_in[23], *bm2 = (const float*)d_in[24];
    const float *Wm3 = (const float*)d_in[25], *bm3 = (const float*)d_in[26];
    float* out = (float*)d_out;

    const int* src = ei;
    const int* dst = ei + NEDGES;

    static cudaStream_t s2 = nullptr;
    static cudaEvent_t evF = nullptr, evJ = nullptr;
    if (s2 == nullptr) {
        cudaStreamCreateWithFlags(&s2, cudaStreamNonBlocking);
        cudaEventCreateWithFlags(&evF, cudaEventDisableTiming);
        cudaEventCreateWithFlags(&evJ, cudaEventDisableTiming);
    }

    // fork: preprocessing + weight splits in s2 overlap layer-1 GEMM in stream 0
    cudaEventRecord(evF, 0);
    cudaStreamWaitEvent(s2, evF, 0);

    zero_kernel<<<512, 256, 0, s2>>>();
    count_kernel<<<(NEDGES + 255) / 256, 256, 0, s2>>>(dst);
    scanA_kernel<<<NSCB, SCAN_B, 0, s2>>>();
    scanB_kernel<<<1, 128, 0, s2>>>();
    scanC_kernel<<<(NNODES + 255) / 256, 256, 0, s2>>>();
    fill_kernel<<<(NEDGES + 255) / 256, 256, 0, s2>>>(src, dst);
    pool_cnt_kernel<<<((NNODES + 63) / 64 + 255) / 256, 256, 0, s2>>>(batch);
    splitW_kernel<2><<<(128 * 256 + 255) / 256, 256, 0, s2>>>(W2, 128, 256);
    splitW_kernel<3><<<(256 * 256 + 255) / 256, 256, 0, s2>>>(W3, 256, 256);

    const int MB = (NNODES + 63) / 64;     // 782 row-tiles

    // layer 1 (transform-first; overlaps preprocessing): x@W1 -> T
    gemm_kernel<0, 0, 1><<<dim3(MB, 2), 256>>>(x, W1, nullptr, nullptr, NNODES, 128, 64);

    cudaEventRecord(evJ, s2);
    cudaStreamWaitEvent(0, evJ, 0);

    aggBN_kernel<32><<<(NNODES + 7) / 8, 256>>>(b1, ga1, be1, m1, v1);     // T->H1

    // layer 2 (agg-first + tensor GEMM): agg(H1) -> T ; split ; T'@W2' -> H2
    aggP_kernel<32, 1><<<(NNODES + 7) / 8, 256>>>();
    splitT_kernel<<<(NNODES * 128 * 3 / 2 + 255) / 256, 256>>>(NNODES * 128 * 3 / 2);
    hmma_kernel<2, 2><<<dim3(MB, 4), 128>>>(b2, ga2, be2, m2, v2, NNODES, 256, 384);

    // layer 3: agg(H2) -> T ; split ; T'@W3' -> H3 (g_H14)
    aggP_kernel<64, 2><<<(NNODES + 3) / 4, 256>>>();
    splitT_kernel<<<(NNODES * 256 * 3 / 2 + 255) / 256, 256>>>(NNODES * 256 * 3 / 2);
    hmma_kernel<3, 1><<<dim3(MB, 4), 128>>>(b3, ga3, be3, m3, v3, NNODES, 256, 768);

    // pooling (reads g_H14)
    pool_feat_kernel<<<(NNODES + 63) / 64, 64>>>(batch);
    finalize_z_kernel<<<(NG * 512 + 255) / 256, 256>>>();

    // MLP head
    gemm_kernel<1, 2, 2><<<dim3(8, 4), 256>>>(nullptr, Wm1, bm1, nullptr, NG, 256, 512);
    gemm_kernel<1, 3, 3><<<dim3(8, 2), 256>>>(nullptr, Wm2, bm2, nullptr, NG, 128, 256);
    mlp3_kernel<<<(NG * 6 + 255) / 256, 256>>>(Wm3, bm3, out);
}

// round 17
// speedup vs baseline: 1.4294x; 1.0536x over previous
#include <cuda_runtime.h>
#include <cuda_fp16.h>
#include <stdint.h>
#include <math.h>

#define NNODES 50000
#define NEDGES 800000
#define NG     512
#define EPSBN  1e-5f
#define SCAN_B 512
#define NSCB   ((NNODES + SCAN_B - 1) / SCAN_B)   // 98

// ---------------- scratch (device globals; no allocations allowed) -----------
__device__ float4       g_T4 [NNODES * 64];   // intermediate (max 256 f wide)
__device__ float4       g_H14[NNODES * 64];   // layer activations (ping)
__device__ float4       g_H24[NNODES * 64];   // layer activations (pong)
__device__ __align__(16) __half g_Tsp [NNODES * 768];  // fp16-split A' (3K wide)
__device__ __align__(16) __half g_W2sp[384 * 256];     // fp16-split W2'
__device__ __align__(16) __half g_W3sp[768 * 256];     // fp16-split W3'
__device__ int          g_cnt[NNODES];
__device__ int          g_off[NNODES + 1];
__device__ int          g_curs[NNODES];
__device__ float        g_dis[NNODES];
__device__ int          g_srcS[NEDGES];
__device__ float        g_normS[NEDGES];
__device__ int          g_bsum[NSCB];
__device__ int          g_boff[NSCB];
__device__ float        g_psum[NG * 256];
__device__ unsigned int g_pmax[NG * 256];
__device__ float        g_pcnt[NG];
__device__ float        g_z  [NG * 512];
__device__ float        g_m1 [NG * 256];
__device__ float        g_m2 [NG * 128];

// ---------------- helpers -----------------------------------------------------
__device__ __forceinline__ unsigned long long pk2(float lo, float hi) {
    unsigned long long r;
    asm("mov.b64 %0, {%1, %2};" : "=l"(r) : "f"(lo), "f"(hi));
    return r;
}
__device__ __forceinline__ void fma2(unsigned long long& d,
                                     unsigned long long a, unsigned long long b) {
    asm("fma.rn.f32x2 %0, %1, %2, %3;" : "=l"(d) : "l"(a), "l"(b), "l"(d));
}
__device__ __forceinline__ float2 upk2(unsigned long long v) {
    float2 f;
    asm("mov.b64 {%0, %1}, %2;" : "=f"(f.x), "=f"(f.y) : "l"(v));
    return f;
}
__device__ __forceinline__ uint32_t s2u(const void* p) {
    return (uint32_t)__cvta_generic_to_shared(p);
}
__device__ __forceinline__ uint32_t packh(__half a, __half b) {
    uint32_t r;
    asm("mov.b32 %0, {%1, %2};" : "=r"(r)
        : "h"(__half_as_ushort(a)), "h"(__half_as_ushort(b)));
    return r;
}
__device__ __forceinline__ void cpasync16(uint32_t dst, const void* src, int nbytes) {
    asm volatile("cp.async.cg.shared.global [%0], [%1], 16, %2;"
                 :: "r"(dst), "l"(src), "r"(nbytes));
}

// ---------------- graph preprocessing ----------------------------------------
__global__ void zero_kernel() {
    int i = blockIdx.x * blockDim.x + threadIdx.x;   // covers 131072
    if (i < NNODES)    g_cnt[i] = 0;
    if (i < NG * 256) { g_psum[i] = 0.f; g_pmax[i] = 0u; }
    if (i < NG)        g_pcnt[i] = 0.f;
}

__global__ void count_kernel(const int* __restrict__ dst) {
    int e = blockIdx.x * blockDim.x + threadIdx.x;
    if (e < NEDGES) atomicAdd(&g_cnt[dst[e]], 1);
}

__global__ void scanA_kernel() {
    __shared__ int sh[SCAN_B];
    int t = threadIdx.x;
    int i = blockIdx.x * SCAN_B + t;
    int v = (i < NNODES) ? g_cnt[i] : 0;
    sh[t] = v;
    __syncthreads();
#pragma unroll
    for (int d = 1; d < SCAN_B; d <<= 1) {
        int u = (t >= d) ? sh[t - d] : 0;
        __syncthreads();
        sh[t] += u;
        __syncthreads();
    }
    if (i < NNODES) g_off[i] = sh[t] - v;
    if (t == SCAN_B - 1) g_bsum[blockIdx.x] = sh[t];
}

__global__ void scanB_kernel() {
    __shared__ int sh[128];
    int t = threadIdx.x;
    int v = (t < NSCB) ? g_bsum[t] : 0;
    sh[t] = v;
    __syncthreads();
#pragma unroll
    for (int d = 1; d < 128; d <<= 1) {
        int u = (t >= d) ? sh[t - d] : 0;
        __syncthreads();
        sh[t] += u;
        __syncthreads();
    }
    if (t < NSCB) g_boff[t] = sh[t] - v;
}

__global__ void scanC_kernel() {
    int i = blockIdx.x * blockDim.x + threadIdx.x;
    if (i < NNODES) {
        int o = g_off[i] + g_boff[i / SCAN_B];
        g_off[i]  = o;
        g_curs[i] = o;
        g_dis[i]  = rsqrtf((float)g_cnt[i] + 1.0f);
    }
    if (i == 0) g_off[NNODES] = NEDGES;
}

__global__ void fill_kernel(const int* __restrict__ src,
                            const int* __restrict__ dst) {
    int e = blockIdx.x * blockDim.x + threadIdx.x;
    if (e < NEDGES) {
        int s = src[e], d = dst[e];
        int p = atomicAdd(&g_curs[d], 1);
        g_srcS[p]  = s;
        g_normS[p] = g_dis[s] * g_dis[d];
    }
}

// ---------------- fp16 split pre-passes ---------------------------------------
// Flat identity: out_half[3f + {0,1,2}] = {h, h, l} for flat float index f.
// Coalesced form: one thread per output uint j = 3q + r covering floats 2q,2q+1.
__global__ void splitT_kernel(int total_uints) {
    int j = blockIdx.x * blockDim.x + threadIdx.x;
    if (j >= total_uints) return;
    int q = j / 3, r = j - q * 3;
    const float* Af = (const float*)g_T4;
    float f0 = Af[2 * q], f1 = Af[2 * q + 1];
    __half h0 = __float2half(f0), l0 = __float2half(f0 - __half2float(h0));
    __half h1 = __float2half(f1), l1 = __float2half(f1 - __half2float(h1));
    uint32_t u;
    if (r == 0)      u = packh(h0, h0);
    else if (r == 1) u = packh(l0, h1);
    else             u = packh(h1, l1);
    ((uint32_t*)g_Tsp)[j] = u;
}

template <int WSEL>
__global__ void splitW_kernel(const float* __restrict__ W, int K, int N) {
    __half* out = (WSEL == 2) ? g_W2sp : g_W3sp;
    int idx = blockIdx.x * blockDim.x + threadIdx.x;
    if (idx >= K * N) return;
    int k = idx / N, n = idx - k * N;
    float a = W[idx];
    __half h = __float2half(a);
    __half l = __float2half(a - __half2float(h));
    out[(3 * k + 0) * N + n] = h;
    out[(3 * k + 1) * N + n] = l;
    out[(3 * k + 2) * N + n] = h;
}

// -------- tensor-core GEMM (R11 smem layout + cp.async double buffering) ------
// C = A'[M,Kp] @ B'[Kp,Nn] + bias + BN + ReLU.  block 64x64, 4 warps (2x2),
// BK=32, mma.m16n8k16 f16->f32.  WSEL: 2/3.  OSEL: 1 -> g_H14, 2 -> g_H24.
template <int WSEL, int OSEL>
__global__ __launch_bounds__(128)
void hmma_kernel(const float* __restrict__ bias, const float* __restrict__ ga,
                 const float* __restrict__ be, const float* __restrict__ mu,
                 const float* __restrict__ va, int M, int Nn, int Kp) {
    const __half* Asp = g_Tsp;
    const __half* Bsp = (WSEL == 2) ? g_W2sp : g_W3sp;
    float* C = (OSEL == 1) ? (float*)g_H14 : (float*)g_H24;

    __shared__ __half As[2][64][40];   // 80B rows (same class as R11)
    __shared__ __half Bs[2][32][72];   // 144B rows
    int tid = threadIdx.x, lane = tid & 31, warp = tid >> 5;
    int m0 = blockIdx.x * 64, n0 = blockIdx.y * 64;
    int wm = (warp >> 1) * 32, wn = (warp & 1) * 32;

    float acc[2][4][4];
#pragma unroll
    for (int a = 0; a < 2; a++)
#pragma unroll
        for (int b = 0; b < 4; b++)
#pragma unroll
            for (int c = 0; c < 4; c++) acc[a][b][c] = 0.f;

    // per-thread load coordinates (same mapping as R11)
    int arow0 = tid >> 2,          aseg0 = tid & 3;         // +  i*128 -> arow+32
    int brow0 = tid >> 3,          bseg0 = tid & 7;         // +  i*128 -> brow+16

    const int NIT = Kp / 32;
    for (int it = 0; it <= NIT; it++) {
        if (it < NIT) {                 // preload tile `it` into buf it&1
            int buf = it & 1;
            int k0 = it * 32;
#pragma unroll
            for (int i = 0; i < 2; i++) {
                int row = arow0 + i * 32;
                int gm = m0 + row;
                int gmc = (gm < M) ? gm : (M - 1);
                cpasync16(s2u(&As[buf][row][aseg0 * 8]),
                          &Asp[(size_t)gmc * Kp + k0 + aseg0 * 8],
                          (gm < M) ? 16 : 0);
            }
#pragma unroll
            for (int i = 0; i < 2; i++) {
                int row = brow0 + i * 16;
                cpasync16(s2u(&Bs[buf][row][bseg0 * 8]),
                          &Bsp[(size_t)(k0 + row) * Nn + n0 + bseg0 * 8], 16);
            }
            asm volatile("cp.async.commit_group;");
        }
        if (it >= 1) {                  // compute tile it-1 from buf (it-1)&1
            if (it < NIT) asm volatile("cp.async.wait_group 1;");
            else          asm volatile("cp.async.wait_group 0;");
            __syncthreads();
            int buf = (it - 1) & 1;
#pragma unroll
            for (int ks = 0; ks < 32; ks += 16) {
                uint32_t af[2][4], bf[4][2];
#pragma unroll
                for (int mf = 0; mf < 2; mf++) {
                    uint32_t addr = s2u(&As[buf][wm + mf * 16 + (lane & 15)][ks + (lane >> 4) * 8]);
                    asm volatile("ldmatrix.sync.aligned.m8n8.x4.shared.b16 {%0,%1,%2,%3}, [%4];"
                        : "=r"(af[mf][0]), "=r"(af[mf][1]), "=r"(af[mf][2]), "=r"(af[mf][3])
                        : "r"(addr));
                }
#pragma unroll
                for (int nf = 0; nf < 2; nf++) {
                    uint32_t r0, r1, r2, r3;
                    uint32_t addr = s2u(&Bs[buf][ks + (lane & 15)][wn + nf * 16 + (lane >> 4) * 8]);
                    asm volatile("ldmatrix.sync.aligned.m8n8.x4.trans.shared.b16 {%0,%1,%2,%3}, [%4];"
                        : "=r"(r0), "=r"(r1), "=r"(r2), "=r"(r3) : "r"(addr));
                    bf[nf * 2][0] = r0;     bf[nf * 2][1] = r1;
                    bf[nf * 2 + 1][0] = r2; bf[nf * 2 + 1][1] = r3;
                }
#pragma unroll
                for (int mf = 0; mf < 2; mf++)
#pragma unroll
                    for (int ng = 0; ng < 4; ng++) {
                        asm volatile(
                            "mma.sync.aligned.m16n8k16.row.col.f32.f16.f16.f32 "
                            "{%0,%1,%2,%3}, {%4,%5,%6,%7}, {%8,%9}, {%0,%1,%2,%3};"
                            : "+f"(acc[mf][ng][0]), "+f"(acc[mf][ng][1]),
                              "+f"(acc[mf][ng][2]), "+f"(acc[mf][ng][3])
                            : "r"(af[mf][0]), "r"(af[mf][1]), "r"(af[mf][2]), "r"(af[mf][3]),
                              "r"(bf[ng][0]), "r"(bf[ng][1]));
                    }
            }
            __syncthreads();
        }
    }

    // epilogue: (acc + bias - mu)*s + be, ReLU
#pragma unroll
    for (int ng = 0; ng < 4; ng++) {
        int n = n0 + wn + ng * 8 + (lane & 3) * 2;
        float s0 = ga[n]     * rsqrtf(va[n]     + EPSBN);
        float s1 = ga[n + 1] * rsqrtf(va[n + 1] + EPSBN);
        float h0 = be[n]     + (bias[n]     - mu[n])     * s0;
        float h1 = be[n + 1] + (bias[n + 1] - mu[n + 1]) * s1;
#pragma unroll
        for (int mf = 0; mf < 2; mf++) {
            int m = m0 + wm + mf * 16 + (lane >> 2);
            if (m < M) {
                C[(size_t)m * Nn + n]     = fmaxf(acc[mf][ng][0] * s0 + h0, 0.f);
                C[(size_t)m * Nn + n + 1] = fmaxf(acc[mf][ng][1] * s1 + h1, 0.f);
            }
            if (m + 8 < M) {
                C[(size_t)(m + 8) * Nn + n]     = fmaxf(acc[mf][ng][2] * s0 + h0, 0.f);
                C[(size_t)(m + 8) * Nn + n + 1] = fmaxf(acc[mf][ng][3] * s1 + h1, 0.f);
            }
        }
    }
}

// ---------------- SIMT GEMM (layer 1 + MLP head) ------------------------------
// ACT: 0=none(+bias if given), 1=bias+GELU
// ASEL: 0=ext, 1=g_T4, 2=g_z, 3=g_m1 ; CSEL: 0=ext, 1=g_T4, 2=g_m1, 3=g_m2
template <int ACT, int ASEL, int CSEL>
__global__ void gemm_kernel(const float* __restrict__ Aext, const float* __restrict__ B,
                            const float* __restrict__ bias, float* __restrict__ Cext,
                            int M, int Nn, int K) {
    const float* A = (ASEL == 0) ? Aext :
                     (ASEL == 1) ? (const float*)g_T4 :
                     (ASEL == 2) ? (const float*)g_z  : (const float*)g_m1;
    float* C = (CSEL == 0) ? Cext :
               (CSEL == 1) ? (float*)g_T4 :
               (CSEL == 2) ? (float*)g_m1 : (float*)g_m2;

    __shared__ float As[16][64];
    __shared__ float Bs[16][64];
    int tid = threadIdx.x;
    int tx = tid & 15, ty = tid >> 4;
    int m0 = blockIdx.x * 64;
    int n0 = blockIdx.y * 64;

    int amI[4], akI[4], bkI[4], bnI[4];
#pragma unroll
    for (int r = 0; r < 4; r++) {
        int idx = tid + r * 256;
        amI[r] = idx >> 4; akI[r] = idx & 15;
        bkI[r] = idx >> 6; bnI[r] = idx & 63;
    }

    unsigned long long acc2[4][2];
#pragma unroll
    for (int i = 0; i < 4; i++) { acc2[i][0] = 0ull; acc2[i][1] = 0ull; }

    float aR[4], bR[4];
#pragma unroll
    for (int r = 0; r < 4; r++) {
        int gm = m0 + amI[r];
        aR[r] = (gm < M) ? A[(size_t)gm * K + akI[r]] : 0.f;
        int gn = n0 + bnI[r];
        bR[r] = (gn < Nn) ? B[(size_t)bkI[r] * Nn + gn] : 0.f;
    }

    for (int k0 = 0; k0 < K; k0 += 16) {
#pragma unroll
        for (int r = 0; r < 4; r++) {
            As[akI[r]][amI[r]] = aR[r];
            Bs[bkI[r]][bnI[r]] = bR[r];
        }
        __syncthreads();
        int kn = k0 + 16;
        if (kn < K) {
#pragma unroll
            for (int r = 0; r < 4; r++) {
                int gm = m0 + amI[r];
                aR[r] = (gm < M) ? A[(size_t)gm * K + kn + akI[r]] : 0.f;
                int gn = n0 + bnI[r];
                bR[r] = (gn < Nn) ? B[(size_t)(kn + bkI[r]) * Nn + gn] : 0.f;
            }
        }
#pragma unroll
        for (int k = 0; k < 16; k++) {
            unsigned long long b0 = *(const unsigned long long*)&Bs[k][tx * 4];
            unsigned long long b1 = *(const unsigned long long*)&Bs[k][tx * 4 + 2];
            float a0 = As[k][ty * 4 + 0];
            float a1 = As[k][ty * 4 + 1];
            float a2 = As[k][ty * 4 + 2];
            float a3 = As[k][ty * 4 + 3];
            unsigned long long p0 = pk2(a0, a0), p1 = pk2(a1, a1);
            unsigned long long p2 = pk2(a2, a2), p3 = pk2(a3, a3);
            fma2(acc2[0][0], p0, b0); fma2(acc2[0][1], p0, b1);
            fma2(acc2[1][0], p1, b0); fma2(acc2[1][1], p1, b1);
            fma2(acc2[2][0], p2, b0); fma2(acc2[2][1], p2, b1);
            fma2(acc2[3][0], p3, b0); fma2(acc2[3][1], p3, b1);
        }
        __syncthreads();
    }
#pragma unroll
    for (int i = 0; i < 4; i++) {
        int m = m0 + ty * 4 + i;
        if (m >= M) continue;
        float2 lo = upk2(acc2[i][0]);
        float2 hi = upk2(acc2[i][1]);
        float v[4] = {lo.x, lo.y, hi.x, hi.y};
#pragma unroll
        for (int j = 0; j < 4; j++) {
            int n = n0 + tx * 4 + j;
            if (n >= Nn) continue;
            float t = v[j];
            if (bias) t += bias[n];
            if (ACT == 1) t = 0.5f * t * (1.0f + erff(t * 0.70710678118654752f));
            C[(size_t)m * Nn + n] = t;
        }
    }
}

// final MLP layer: out[G, 6] = g_m2[G, 128] @ Wm3[128, 6] + bm3
__global__ void mlp3_kernel(const float* __restrict__ Wm3,
                            const float* __restrict__ bm3,
                            float* __restrict__ out) {
    int idx = blockIdx.x * blockDim.x + threadIdx.x;
    if (idx >= NG * 6) return;
    int m = idx / 6, n = idx % 6;
    const float* row = &g_m2[m * 128];
    float s = 0.f;
#pragma unroll 8
    for (int k = 0; k < 128; k++) s += row[k] * Wm3[k * 6 + n];
    out[idx] = s + bm3[n];
}

// ------- agg with BN+ReLU epilogue (layer 1: reads g_T4, writes g_H14) -------
template <int D4>
__global__ void aggBN_kernel(const float* __restrict__ b,  const float* __restrict__ ga,
                             const float* __restrict__ be, const float* __restrict__ mm,
                             const float* __restrict__ vv) {
    constexpr int NODES = 256 / D4;
    int node = blockIdx.x * NODES + (threadIdx.x / D4);
    int c    = threadIdx.x & (D4 - 1);
    if (node >= NNODES) return;

    float dn = g_dis[node];
    float w0 = dn * dn;
    float4 t = g_T4[(size_t)node * D4 + c];
    float4 acc = make_float4(t.x * w0, t.y * w0, t.z * w0, t.w * w0);

    int e = g_off[node], e1 = g_off[node + 1];
    for (; e + 4 <= e1; e += 4) {
        int s0 = g_srcS[e], s1 = g_srcS[e+1], s2 = g_srcS[e+2], s3 = g_srcS[e+3];
        float n0 = g_normS[e], n1 = g_normS[e+1], n2 = g_normS[e+2], n3 = g_normS[e+3];
        float4 t0 = g_T4[(size_t)s0 * D4 + c];
        float4 t1 = g_T4[(size_t)s1 * D4 + c];
        float4 t2 = g_T4[(size_t)s2 * D4 + c];
        float4 t3 = g_T4[(size_t)s3 * D4 + c];
        acc.x += t0.x*n0 + t1.x*n1 + t2.x*n2 + t3.x*n3;
        acc.y += t0.y*n0 + t1.y*n1 + t2.y*n2 + t3.y*n3;
        acc.z += t0.z*n0 + t1.z*n1 + t2.z*n2 + t3.z*n3;
        acc.w += t0.w*n0 + t1.w*n1 + t2.w*n2 + t3.w*n3;
    }
    for (; e < e1; e++) {
        int   s = g_srcS[e];
        float w = g_normS[e];
        float4 ts = g_T4[(size_t)s * D4 + c];
        acc.x += ts.x * w; acc.y += ts.y * w;
        acc.z += ts.z * w; acc.w += ts.w * w;
    }

    float4 o;
#pragma unroll
    for (int q = 0; q < 4; q++) {
        int n = c * 4 + q;
        float s  = ga[n] * rsqrtf(vv[n] + EPSBN);
        float v  = ((&acc.x)[q] + b[n] - mm[n]) * s + be[n];
        (&o.x)[q] = fmaxf(v, 0.f);
    }
    g_H14[(size_t)node * D4 + c] = o;
}

// ------- plain agg (no epilogue): reads H-buffer, writes g_T4 ----------------
template <int D4, int ISEL>
__global__ void aggP_kernel() {
    const float4* In = (ISEL == 1) ? g_H14 : g_H24;
    constexpr int NODES = 256 / D4;
    int node = blockIdx.x * NODES + (threadIdx.x / D4);
    int c    = threadIdx.x & (D4 - 1);
    if (node >= NNODES) return;

    float dn = g_dis[node];
    float w0 = dn * dn;
    float4 t = In[(size_t)node * D4 + c];
    float4 acc = make_float4(t.x * w0, t.y * w0, t.z * w0, t.w * w0);

    int e = g_off[node], e1 = g_off[node + 1];
    for (; e + 4 <= e1; e += 4) {
        int s0 = g_srcS[e], s1 = g_srcS[e+1], s2 = g_srcS[e+2], s3 = g_srcS[e+3];
        float n0 = g_normS[e], n1 = g_normS[e+1], n2 = g_normS[e+2], n3 = g_normS[e+3];
        float4 t0 = In[(size_t)s0 * D4 + c];
        float4 t1 = In[(size_t)s1 * D4 + c];
        float4 t2 = In[(size_t)s2 * D4 + c];
        float4 t3 = In[(size_t)s3 * D4 + c];
        acc.x += t0.x*n0 + t1.x*n1 + t2.x*n2 + t3.x*n3;
        acc.y += t0.y*n0 + t1.y*n1 + t2.y*n2 + t3.y*n3;
        acc.z += t0.z*n0 + t1.z*n1 + t2.z*n2 + t3.z*n3;
        acc.w += t0.w*n0 + t1.w*n1 + t2.w*n2 + t3.w*n3;
    }
    for (; e < e1; e++) {
        int   s = g_srcS[e];
        float w = g_normS[e];
        float4 ts = In[(size_t)s * D4 + c];
        acc.x += ts.x * w; acc.y += ts.y * w;
        acc.z += ts.z * w; acc.w += ts.w * w;
    }
    g_T4[(size_t)node * D4 + c] = acc;
}

// ---------------- pooling (sorted batch; 4 independent 16-row segments) -------
__global__ void pool_feat_kernel(const int* __restrict__ batch) {
    int c   = threadIdx.x & 63;           // float4 column (d = 256)
    int seg = threadIdx.x >> 6;           // 0..3
    int i0  = blockIdx.x * 64 + seg * 16;
    if (i0 >= NNODES) return;
    int i1 = min(i0 + 16, NNODES);
    int cur = batch[i0];
    float4 s  = make_float4(0, 0, 0, 0);
    float4 mx = make_float4(0, 0, 0, 0);
    for (int i = i0; i < i1; i++) {
        int g = batch[i];
        if (g != cur) {
            int base = cur * 256 + c * 4;
            atomicAdd(&g_psum[base + 0], s.x); atomicAdd(&g_psum[base + 1], s.y);
            atomicAdd(&g_psum[base + 2], s.z); atomicAdd(&g_psum[base + 3], s.w);
            atomicMax(&g_pmax[base + 0], __float_as_uint(mx.x));
            atomicMax(&g_pmax[base + 1], __float_as_uint(mx.y));
            atomicMax(&g_pmax[base + 2], __float_as_uint(mx.z));
            atomicMax(&g_pmax[base + 3], __float_as_uint(mx.w));
            cur = g; s = make_float4(0, 0, 0, 0); mx = make_float4(0, 0, 0, 0);
        }
        float4 hv = g_H14[(size_t)i * 64 + c];
        s.x += hv.x; s.y += hv.y; s.z += hv.z; s.w += hv.w;
        mx.x = fmaxf(mx.x, hv.x); mx.y = fmaxf(mx.y, hv.y);
        mx.z = fmaxf(mx.z, hv.z); mx.w = fmaxf(mx.w, hv.w);
    }
    int base = cur * 256 + c * 4;
    atomicAdd(&g_psum[base + 0], s.x); atomicAdd(&g_psum[base + 1], s.y);
    atomicAdd(&g_psum[base + 2], s.z); atomicAdd(&g_psum[base + 3], s.w);
    atomicMax(&g_pmax[base + 0], __float_as_uint(mx.x));
    atomicMax(&g_pmax[base + 1], __float_as_uint(mx.y));
    atomicMax(&g_pmax[base + 2], __float_as_uint(mx.z));
    atomicMax(&g_pmax[base + 3], __float_as_uint(mx.w));
}

__global__ void pool_cnt_kernel(const int* __restrict__ batch) {
    int t  = blockIdx.x * blockDim.x + threadIdx.x;
    int i0 = t * 64;
    if (i0 >= NNODES) return;
    int i1 = min(i0 + 64, NNODES);
    int cur = batch[i0];
    int run = 0;
    for (int i = i0; i < i1; i++) {
        int g = batch[i];
        if (g != cur) { atomicAdd(&g_pcnt[cur], (float)run); cur = g; run = 0; }
        run++;
    }
    atomicAdd(&g_pcnt[cur], (float)run);
}

__global__ void finalize_z_kernel() {
    int idx = blockIdx.x * blockDim.x + threadIdx.x;
    if (idx >= NG * 512) return;
    int g = idx >> 9, c = idx & 511;
    if (c < 256) g_z[idx] = g_psum[g * 256 + c] / fmaxf(g_pcnt[g], 1.0f);
    else         g_z[idx] = __uint_as_float(g_pmax[g * 256 + (c - 256)]);
}

// ---------------- launch ------------------------------------------------------
extern "C" void kernel_launch(void* const* d_in, const int* in_sizes, int n_in,
                              void* d_out, int out_size) {
    const float* x     = (const float*)d_in[0];
    const int*   ei    = (const int*)d_in[1];
    const int*   batch = (const int*)d_in[2];
    const float *W1 = (const float*)d_in[3],  *b1 = (const float*)d_in[4],
                *ga1 = (const float*)d_in[5], *be1 = (const float*)d_in[6],
                *m1 = (const float*)d_in[7],  *v1 = (const float*)d_in[8];
    const float *W2 = (const float*)d_in[9],  *b2 = (const float*)d_in[10],
                *ga2 = (const float*)d_in[11],*be2 = (const float*)d_in[12],
                *m2 = (const float*)d_in[13], *v2 = (const float*)d_in[14];
    const float *W3 = (const float*)d_in[15], *b3 = (const float*)d_in[16],
                *ga3 = (const float*)d_in[17],*be3 = (const float*)d_in[18],
                *m3 = (const float*)d_in[19], *v3 = (const float*)d_in[20];
    const float *Wm1 = (const float*)d_in[21], *bm1 = (const float*)d_in[22];
    const float *Wm2 = (const float*)d_in[23], *bm2 = (const float*)d_in[24];
    const float *Wm3 = (const float*)d_in[25], *bm3 = (const float*)d_in[26];
    float* out = (float*)d_out;

    const int* src = ei;
    const int* dst = ei + NEDGES;

    static cudaStream_t s2 = nullptr;
    static cudaEvent_t evF = nullptr, evJ = nullptr;
    if (s2 == nullptr) {
        cudaStreamCreateWithFlags(&s2, cudaStreamNonBlocking);
        cudaEventCreateWithFlags(&evF, cudaEventDisableTiming);
        cudaEventCreateWithFlags(&evJ, cudaEventDisableTiming);
    }

    // fork: preprocessing + weight splits in s2 overlap layer-1 GEMM in stream 0
    cudaEventRecord(evF, 0);
    cudaStreamWaitEvent(s2, evF, 0);

    zero_kernel<<<512, 256, 0, s2>>>();
    count_kernel<<<(NEDGES + 255) / 256, 256, 0, s2>>>(dst);
    scanA_kernel<<<NSCB, SCAN_B, 0, s2>>>();
    scanB_kernel<<<1, 128, 0, s2>>>();
    scanC_kernel<<<(NNODES + 255) / 256, 256, 0, s2>>>();
    fill_kernel<<<(NEDGES + 255) / 256, 256, 0, s2>>>(src, dst);
    pool_cnt_kernel<<<((NNODES + 63) / 64 + 255) / 256, 256, 0, s2>>>(batch);
    splitW_kernel<2><<<(128 * 256 + 255) / 256, 256, 0, s2>>>(W2, 128, 256);
    splitW_kernel<3><<<(256 * 256 + 255) / 256, 256, 0, s2>>>(W3, 256, 256);

    const int MB = (NNODES + 63) / 64;     // 782 row-tiles

    // layer 1 (transform-first; overlaps preprocessing): x@W1 -> T
    gemm_kernel<0, 0, 1><<<dim3(MB, 2), 256>>>(x, W1, nullptr, nullptr, NNODES, 128, 64);

    cudaEventRecord(evJ, s2);
    cudaStreamWaitEvent(0, evJ, 0);

    aggBN_kernel<32><<<(NNODES + 7) / 8, 256>>>(b1, ga1, be1, m1, v1);     // T->H1

    // layer 2 (agg-first + tensor GEMM): agg(H1) -> T ; split ; T'@W2' -> H2
    aggP_kernel<32, 1><<<(NNODES + 7) / 8, 256>>>();
    splitT_kernel<<<(NNODES * 128 * 3 / 2 + 255) / 256, 256>>>(NNODES * 128 * 3 / 2);
    hmma_kernel<2, 2><<<dim3(MB, 4), 128>>>(b2, ga2, be2, m2, v2, NNODES, 256, 384);

    // layer 3: agg(H2) -> T ; split ; T'@W3' -> H3 (g_H14)
    aggP_kernel<64, 2><<<(NNODES + 3) / 4, 256>>>();
    splitT_kernel<<<(NNODES * 256 * 3 / 2 + 255) / 256, 256>>>(NNODES * 256 * 3 / 2);
    hmma_kernel<3, 1><<<dim3(MB, 4), 128>>>(b3, ga3, be3, m3, v3, NNODES, 256, 768);

    // pooling (reads g_H14)
    pool_feat_kernel<<<(NNODES + 63) / 64, 256>>>(batch);
    finalize_z_kernel<<<(NG * 512 + 255) / 256, 256>>>();

    // MLP head
    gemm_kernel<1, 2, 2><<<dim3(8, 4), 256>>>(nullptr, Wm1, bm1, nullptr, NG, 256, 512);
    gemm_kernel<1, 3, 3><<<dim3(8, 2), 256>>>(nullptr, Wm2, bm2, nullptr, NG, 128, 256);
    mlp3_kernel<<<(NG * 6 + 255) / 256, 256>>>(Wm3, bm3, out);
}